// round 11
// baseline (speedup 1.0000x reference)
#include <cuda_runtime.h>
#include <cstdint>

#define FULLM 0xffffffffu

namespace {
constexpr int T_STEPS = 128;
constexpr int NCH = 17;
constexpr int IMG_FLOATS = T_STEPS * NCH;       // 2176
constexpr int IMG_F4 = IMG_FLOATS / 4;          // 544
constexpr int IMG_BYTES = IMG_FLOATS * 4;       // 8704
constexpr int TRAJ = 2;                         // trajectories per CTA
}

// ---- JAX Brent-Kung 128-scan, decomposed: per-warp upsweep, 4-wide top
// tree through smem totals, per-warp downsweep with prefix injection.
// Bit-identical to the flat jnp.cumsum association (verified R4-R10). ----

__device__ __forceinline__ float scan_up1(float r, int lane) {
#pragma unroll
    for (int h = 1; h <= 16; h <<= 1) {
        float u = __shfl_up_sync(FULLM, r, h);
        if ((lane & (2 * h - 1)) == (2 * h - 1)) r = __fadd_rn(u, r);
    }
    return r;
}

__device__ __forceinline__ void scan_up2(float& a, float& b, int lane) {
#pragma unroll
    for (int h = 1; h <= 16; h <<= 1) {
        float ua = __shfl_up_sync(FULLM, a, h);
        float ub = __shfl_up_sync(FULLM, b, h);
        if ((lane & (2 * h - 1)) == (2 * h - 1)) {
            a = __fadd_rn(ua, a);
            b = __fadd_rn(ub, b);
        }
    }
}

__device__ __forceinline__ float scan_down1(float r, int lane, int w,
                                            const float* __restrict__ T) {
    const float s1 = __fadd_rn(T[0], T[1]);
    const float S2 = __fadd_rn(s1, T[2]);
    const float S3 = __fadd_rn(s1, __fadd_rn(T[2], T[3]));
    const float E  = (w == 1) ? T[0] : (w == 2) ? s1 : S2;
    const float Sw = (w == 0) ? T[0] : (w == 1) ? s1 : (w == 2) ? S2 : S3;
    if (lane == 31) r = Sw;
#pragma unroll
    for (int h = 16; h >= 1; h >>= 1) {
        float u = __shfl_up_sync(FULLM, r, h);
        if (lane == h - 1) u = E;
        const bool act = ((lane & (2 * h - 1)) == (h - 1)) &&
                         (w > 0 || lane >= 2 * h);
        if (act) r = __fadd_rn(u, r);
    }
    return r;
}

__device__ __forceinline__ void scan_down2(float& a, float& b, int lane, int w,
                                           const float* __restrict__ Ta,
                                           const float* __restrict__ Tb) {
    const float s1a = __fadd_rn(Ta[0], Ta[1]);
    const float S2a = __fadd_rn(s1a, Ta[2]);
    const float S3a = __fadd_rn(s1a, __fadd_rn(Ta[2], Ta[3]));
    const float Ea  = (w == 1) ? Ta[0] : (w == 2) ? s1a : S2a;
    const float Swa = (w == 0) ? Ta[0] : (w == 1) ? s1a : (w == 2) ? S2a : S3a;
    const float s1b = __fadd_rn(Tb[0], Tb[1]);
    const float S2b = __fadd_rn(s1b, Tb[2]);
    const float S3b = __fadd_rn(s1b, __fadd_rn(Tb[2], Tb[3]));
    const float Eb  = (w == 1) ? Tb[0] : (w == 2) ? s1b : S2b;
    const float Swb = (w == 0) ? Tb[0] : (w == 1) ? s1b : (w == 2) ? S2b : S3b;
    if (lane == 31) { a = Swa; b = Swb; }
#pragma unroll
    for (int h = 16; h >= 1; h >>= 1) {
        float ua = __shfl_up_sync(FULLM, a, h);
        float ub = __shfl_up_sync(FULLM, b, h);
        if (lane == h - 1) { ua = Ea; ub = Eb; }
        const bool act = ((lane & (2 * h - 1)) == (h - 1)) &&
                         (w > 0 || lane >= 2 * h);
        if (act) { a = __fadd_rn(ua, a); b = __fadd_rn(ub, b); }
    }
}

__device__ __forceinline__ void cp_async16(float4* dst_smem, const float4* src_gmem) {
    uint32_t s = (uint32_t)__cvta_generic_to_shared(dst_smem);
    asm volatile("cp.async.cg.shared.global [%0], [%1], 16;" ::
                 "r"(s), "l"(src_gmem));
}

__global__ __launch_bounds__(TRAJ * 128, 6)
void car_dyn_kernel(const float* __restrict__ state,
                    const float* __restrict__ pact,
                    const float* __restrict__ Hmap,
                    const float* __restrict__ Nrm,
                    float* __restrict__ out_states,
                    float* __restrict__ out_pa)
{
    __shared__ __align__(16) float img[TRAJ][IMG_FLOATS];   // 2 x 8704 B
    __shared__ float tot[TRAJ][5][4];
    __shared__ float bnd[TRAJ][4][2];

    const int tid  = threadIdx.x;
    const int ttid = tid & 127;          // thread-within-trajectory (timestep)
    const int lane = tid & 31;
    const int w    = (tid >> 5) & 3;     // warp-within-trajectory
    const int j    = tid >> 7;           // trajectory slot 0/1
    const int k    = blockIdx.x * TRAJ + j;

    float4* img4 = reinterpret_cast<float4*>(img[j]);
    const float4* src4 = reinterpret_cast<const float4*>(state) + (size_t)k * IMG_F4;
#pragma unroll
    for (int i = 0; i < 4; ++i) cp_async16(&img4[ttid + 128 * i], &src4[ttid + 128 * i]);
    if (ttid < 32) cp_async16(&img4[512 + ttid], &src4[512 + ttid]);
    asm volatile("cp.async.commit_group;" ::: "memory");

    const float2 pa = reinterpret_cast<const float2*>(pact)[(size_t)k * T_STEPS + ttid];

    // ---- scans 1&2: cumsum(pa * DT) (overlap with in-copy) ----
    float r0 = __fmul_rn(pa.x, 0.02f);
    float r1 = __fmul_rn(pa.y, 0.02f);
    scan_up2(r0, r1, lane);
    if (lane == 31) { tot[j][0][w] = r0; tot[j][1][w] = r1; }

    asm volatile("cp.async.wait_group 0;" ::: "memory");
    __syncthreads();   // (1) images + warp totals ready

    scan_down2(r0, r1, lane, w, tot[j][0], tot[j][1]);

    float* rec = img[j] + ttid * NCH;    // stride 17 -> conflict-free scalars

    // ---- controls (fma exact: x4 is exact so fma == mul+add bitwise) ----
    const float s15 = rec[15], s16 = rec[16];
    float c0 = fminf(fmaxf(__fmaf_rn(4.0f, r0, s15), -1.f), 1.f);
    float c1 = fminf(fmaxf(__fmaf_rn(4.0f, r1, s16), 0.f), 0.5f);
    const float cm0 = __fsub_rn(c0, s15);
    const float cm1 = __fsub_rn(c1, s16);
    rec[15] = c0; rec[16] = c1;
    rec[7] = 0.f; rec[8] = 0.f;          // vy, vz (ch9 = ax passes through)

    // ---- dynamics elementwise (gather-feeding chain: exact) ----
    const float Kc = __fmul_rn(tanf(c0), 2.0f);
    const float vx = __fmul_rn(c1, 17.0f);
    const float dS = __fmul_rn(vx, 0.02f);
    const float w1 = __fmul_rn(vx, Kc);
    const float a0 = fminf(fmaxf(__fmul_rn(vx, w1), -14.f), 14.f);
    const float wz = __fdiv_rn(a0, fmaxf(vx, 1.f));   // exact: feeds gather
    rec[6] = vx; rec[14] = wz;

    // ---- scan 3 upsweep (wz) + cm boundary exchange, one sync ----
    float r2 = scan_up1(wz, lane);
    if (lane == 31) { tot[j][2][w] = r2; bnd[j][w][0] = cm0; bnd[j][w][1] = cm1; }
    __syncthreads();   // (2)

    // ---- new_pa straight to global (terminal: x12.5 == /0.08, ~1ulp) ----
    {
        float pm0 = __shfl_up_sync(FULLM, cm0, 1);
        float pm1 = __shfl_up_sync(FULLM, cm1, 1);
        if (lane == 0 && w > 0) { pm0 = bnd[j][w - 1][0]; pm1 = bnd[j][w - 1][1]; }
        float np0 = __fmul_rn(__fsub_rn(cm0, pm0), 12.5f);
        float np1 = __fmul_rn(__fsub_rn(cm1, pm1), 12.5f);
        if (ttid == 0) { np0 = pa.x; np1 = pa.y; }
        reinterpret_cast<float2*>(out_pa)[(size_t)k * T_STEPS + ttid] =
            make_float2(np0, np1);
    }

    r2 = scan_down1(r2, lane, w, tot[j][2]);
    const float yaw = __fadd_rn(rec[5], __fmul_rn(0.02f, r2));
    rec[5] = yaw;
    float sy, cy;
    sincosf(yaw, &sy, &cy);

    // ---- scans 4&5: x, y ----
    float r3 = __fmul_rn(dS, cy);
    float r4 = __fmul_rn(dS, sy);
    scan_up2(r3, r4, lane);
    if (lane == 31) { tot[j][3][w] = r3; tot[j][4][w] = r4; }
    __syncthreads();   // (3)
    scan_down2(r3, r4, lane, w, tot[j][3], tot[j][4]);
    const float x = __fadd_rn(rec[0], r3);
    const float y = __fadd_rn(rec[1], r4);
    rec[0] = x; rec[1] = y;

    // ---- BEV gather ----
    int iX = (int)(__fmul_rn(__fadd_rn(x, 32.f), 4.f));
    int iY = (int)(__fmul_rn(__fadd_rn(y, 32.f), 4.f));
    iX = min(max(iX, 0), 255);
    iY = min(max(iY, 0), 255);
    const int g = iY * 256 + iX;
    const float z  = __ldg(Hmap + g);
    const float nx = __ldg(Nrm + 3 * g + 0);
    const float ny = __ldg(Nrm + 3 * g + 1);
    const float nz = __ldg(Nrm + 3 * g + 2);

    const float lz = __fsub_rn(__fmul_rn(nx, sy), __fmul_rn(ny, cy));
    const float lx = __fsub_rn(0.f, __fmul_rn(nz, sy));
    const float ly = __fmul_rn(nz, cy);
    const float roll = asinf(lz);
    const float fz = __fsub_rn(__fmul_rn(lx, ny), __fmul_rn(ly, nx));
    const float pitch = -asinf(fz);
    rec[2] = z; rec[3] = roll; rec[4] = pitch;

    // ---- roll/pitch boundary exchange + diffs (terminal: x50 == /0.02) ----
    if (lane == 31) { bnd[j][w][0] = roll; bnd[j][w][1] = pitch; }
    __syncthreads();   // (4)
    float pr = __shfl_up_sync(FULLM, roll, 1);
    float pp = __shfl_up_sync(FULLM, pitch, 1);
    if (lane == 0 && w > 0) { pr = bnd[j][w - 1][0]; pp = bnd[j][w - 1][1]; }
    float wxv = __fmul_rn(__fsub_rn(roll, pr), 50.0f);
    float wyv = __fmul_rn(__fsub_rn(pitch, pp), 50.0f);
    if (ttid == 0) { wxv = rec[12]; wyv = rec[13]; }   // input ch12/13 intact
    const float ay = __fadd_rn(__fmul_rn(vx, wz), __fmul_rn(9.8f, lz));
    const float az = __fadd_rn(__fmul_rn(__fsub_rn(0.f, vx), wyv),
                               __fmul_rn(9.8f, nz));
    rec[10] = ay; rec[11] = az; rec[12] = wxv; rec[13] = wyv;

    __syncthreads();   // (5) images final

    // ---- bulk DMA: smem -> global, one per trajectory ----
    if (ttid == 0) {
        float* dst = out_states + (size_t)k * IMG_FLOATS;
        const uint32_t img_s = (uint32_t)__cvta_generic_to_shared(img[j]);
        asm volatile("fence.proxy.async.shared::cta;" ::: "memory");
        asm volatile(
            "cp.async.bulk.global.shared::cta.bulk_group [%0], [%1], %2;"
            :: "l"(dst), "r"(img_s), "r"((uint32_t)IMG_BYTES) : "memory");
        asm volatile("cp.async.bulk.commit_group;" ::: "memory");
        asm volatile("cp.async.bulk.wait_group.read 0;" ::: "memory");
    }
}

extern "C" void kernel_launch(void* const* d_in, const int* in_sizes, int n_in,
                              void* d_out, int out_size)
{
    const float* state = (const float*)d_in[0];
    const float* pact  = (const float*)d_in[1];
    const float* Hmap  = (const float*)d_in[2];
    const float* Nrm   = (const float*)d_in[3];

    const int K = (in_sizes[1] / 2) / T_STEPS;
    float* out_states = (float*)d_out;
    float* out_pa     = (float*)d_out + (size_t)in_sizes[0];

    car_dyn_kernel<<<K / TRAJ, TRAJ * 128>>>(state, pact, Hmap, Nrm,
                                             out_states, out_pa);
}

// round 12
// speedup vs baseline: 1.0715x; 1.0715x over previous
#include <cuda_runtime.h>
#include <cstdint>

#define FULLM 0xffffffffu

namespace {
constexpr int T_STEPS = 128;
constexpr int NCH = 17;
constexpr int IMG_FLOATS = T_STEPS * NCH;       // 2176
constexpr int IMG_F4 = IMG_FLOATS / 4;          // 544
constexpr int IMG_BYTES = IMG_FLOATS * 4;       // 8704
}

// ---- JAX Brent-Kung 128-scan, decomposed: per-warp upsweep, 4-wide top
// tree through smem totals, per-warp downsweep with prefix injection.
// Bit-identical to the flat jnp.cumsum association (verified R4-R11). ----

__device__ __forceinline__ float scan_up1(float r, int lane) {
#pragma unroll
    for (int h = 1; h <= 16; h <<= 1) {
        float u = __shfl_up_sync(FULLM, r, h);
        if ((lane & (2 * h - 1)) == (2 * h - 1)) r = __fadd_rn(u, r);
    }
    return r;
}

__device__ __forceinline__ void scan_up2(float& a, float& b, int lane) {
#pragma unroll
    for (int h = 1; h <= 16; h <<= 1) {
        float ua = __shfl_up_sync(FULLM, a, h);
        float ub = __shfl_up_sync(FULLM, b, h);
        if ((lane & (2 * h - 1)) == (2 * h - 1)) {
            a = __fadd_rn(ua, a);
            b = __fadd_rn(ub, b);
        }
    }
}

__device__ __forceinline__ float scan_down1(float r, int lane, int w,
                                            const float* __restrict__ T) {
    const float s1 = __fadd_rn(T[0], T[1]);
    const float S2 = __fadd_rn(s1, T[2]);
    const float S3 = __fadd_rn(s1, __fadd_rn(T[2], T[3]));
    const float E  = (w == 1) ? T[0] : (w == 2) ? s1 : S2;
    const float Sw = (w == 0) ? T[0] : (w == 1) ? s1 : (w == 2) ? S2 : S3;
    if (lane == 31) r = Sw;
#pragma unroll
    for (int h = 16; h >= 1; h >>= 1) {
        float u = __shfl_up_sync(FULLM, r, h);
        if (lane == h - 1) u = E;
        const bool act = ((lane & (2 * h - 1)) == (h - 1)) &&
                         (w > 0 || lane >= 2 * h);
        if (act) r = __fadd_rn(u, r);
    }
    return r;
}

__device__ __forceinline__ void scan_down2(float& a, float& b, int lane, int w,
                                           const float* __restrict__ Ta,
                                           const float* __restrict__ Tb) {
    const float s1a = __fadd_rn(Ta[0], Ta[1]);
    const float S2a = __fadd_rn(s1a, Ta[2]);
    const float S3a = __fadd_rn(s1a, __fadd_rn(Ta[2], Ta[3]));
    const float Ea  = (w == 1) ? Ta[0] : (w == 2) ? s1a : S2a;
    const float Swa = (w == 0) ? Ta[0] : (w == 1) ? s1a : (w == 2) ? S2a : S3a;
    const float s1b = __fadd_rn(Tb[0], Tb[1]);
    const float S2b = __fadd_rn(s1b, Tb[2]);
    const float S3b = __fadd_rn(s1b, __fadd_rn(Tb[2], Tb[3]));
    const float Eb  = (w == 1) ? Tb[0] : (w == 2) ? s1b : S2b;
    const float Swb = (w == 0) ? Tb[0] : (w == 1) ? s1b : (w == 2) ? S2b : S3b;
    if (lane == 31) { a = Swa; b = Swb; }
#pragma unroll
    for (int h = 16; h >= 1; h >>= 1) {
        float ua = __shfl_up_sync(FULLM, a, h);
        float ub = __shfl_up_sync(FULLM, b, h);
        if (lane == h - 1) { ua = Ea; ub = Eb; }
        const bool act = ((lane & (2 * h - 1)) == (h - 1)) &&
                         (w > 0 || lane >= 2 * h);
        if (act) { a = __fadd_rn(ua, a); b = __fadd_rn(ub, b); }
    }
}

__device__ __forceinline__ void cp_async16(float4* dst_smem, const float4* src_gmem) {
    uint32_t s = (uint32_t)__cvta_generic_to_shared(dst_smem);
    asm volatile("cp.async.cg.shared.global [%0], [%1], 16;" ::
                 "r"(s), "l"(src_gmem));
}

__global__ __launch_bounds__(128, 16)
void car_dyn_kernel(const float* __restrict__ state,
                    const float* __restrict__ pact,
                    const float* __restrict__ Hmap,
                    const float* __restrict__ Nrm,
                    float* __restrict__ out_states,
                    float* __restrict__ out_pa)
{
    __shared__ __align__(16) float img[IMG_FLOATS];   // 8704 B working image
    __shared__ float tot[5][4];
    __shared__ float bnd[4][2];

    const int tid  = threadIdx.x;
    const int lane = tid & 31;
    const int w    = tid >> 5;
    const int k    = blockIdx.x;

    float4* img4 = reinterpret_cast<float4*>(img);
    const float4* src4 = reinterpret_cast<const float4*>(state) + (size_t)k * IMG_F4;
#pragma unroll
    for (int i = 0; i < 4; ++i) cp_async16(&img4[tid + 128 * i], &src4[tid + 128 * i]);
    if (tid < 32) cp_async16(&img4[512 + tid], &src4[512 + tid]);
    asm volatile("cp.async.commit_group;" ::: "memory");

    const float2 pa = reinterpret_cast<const float2*>(pact)[(size_t)k * T_STEPS + tid];

    // ---- scans 1&2: cumsum(pa * DT) (overlap with in-copy) ----
    float r0 = __fmul_rn(pa.x, 0.02f);
    float r1 = __fmul_rn(pa.y, 0.02f);
    scan_up2(r0, r1, lane);
    if (lane == 31) { tot[0][w] = r0; tot[1][w] = r1; }

    asm volatile("cp.async.wait_group 0;" ::: "memory");
    __syncthreads();   // (1) image + warp totals ready

    scan_down2(r0, r1, lane, w, tot[0], tot[1]);

    float* rec = img + tid * NCH;   // base 17*tid -> conflict-free scalars

    // ---- controls (clip(clip(v,-1,1),0,0.5) == clip(v,0,0.5), exact) ----
    const float s15 = rec[15], s16 = rec[16];
    float c0 = fminf(fmaxf(__fadd_rn(s15, __fmul_rn(4.0f, r0)), -1.f), 1.f);
    float c1 = fminf(fmaxf(__fadd_rn(s16, __fmul_rn(4.0f, r1)), 0.f), 0.5f);
    const float cm0 = __fsub_rn(c0, s15);
    const float cm1 = __fsub_rn(c1, s16);
    rec[15] = c0; rec[16] = c1;
    rec[7] = 0.f; rec[8] = 0.f;      // vy, vz (ch9 = ax passes through)

    // ---- dynamics elementwise (gather-feeding chain: exact) ----
    const float Kc = __fmul_rn(tanf(c0), 2.0f);       // /0.5 exact
    const float vx = __fmul_rn(c1, 17.0f);
    const float dS = __fmul_rn(vx, 0.02f);
    const float w1 = __fmul_rn(vx, Kc);
    const float a0 = fminf(fmaxf(__fmul_rn(vx, w1), -14.f), 14.f);
    const float wz = __fdiv_rn(a0, fmaxf(vx, 1.f));   // exact: feeds yaw->x,y->gather
    rec[6] = vx; rec[14] = wz;

    // ---- scan 3 upsweep (wz) + cm boundary exchange, one sync ----
    float r2 = scan_up1(wz, lane);
    if (lane == 31) { tot[2][w] = r2; bnd[w][0] = cm0; bnd[w][1] = cm1; }
    __syncthreads();   // (2)

    // ---- new_pa straight to global (terminal output: x12.5 == /0.08, ~1ulp) ----
    {
        float pm0 = __shfl_up_sync(FULLM, cm0, 1);
        float pm1 = __shfl_up_sync(FULLM, cm1, 1);
        if (lane == 0 && w > 0) { pm0 = bnd[w - 1][0]; pm1 = bnd[w - 1][1]; }
        float np0 = __fmul_rn(__fsub_rn(cm0, pm0), 12.5f);
        float np1 = __fmul_rn(__fsub_rn(cm1, pm1), 12.5f);
        if (tid == 0) { np0 = pa.x; np1 = pa.y; }
        reinterpret_cast<float2*>(out_pa)[(size_t)k * T_STEPS + tid] =
            make_float2(np0, np1);
    }

    r2 = scan_down1(r2, lane, w, tot[2]);
    const float yaw = __fadd_rn(rec[5], __fmul_rn(0.02f, r2));
    rec[5] = yaw;
    float sy, cy;
    sincosf(yaw, &sy, &cy);

    // ---- scans 4&5: x, y ----
    float r3 = __fmul_rn(dS, cy);
    float r4 = __fmul_rn(dS, sy);
    scan_up2(r3, r4, lane);
    if (lane == 31) { tot[3][w] = r3; tot[4][w] = r4; }
    __syncthreads();   // (3)
    scan_down2(r3, r4, lane, w, tot[3], tot[4]);
    const float x = __fadd_rn(rec[0], r3);
    const float y = __fadd_rn(rec[1], r4);
    rec[0] = x; rec[1] = y;

    // ---- BEV gather ----
    int iX = (int)(__fmul_rn(__fadd_rn(x, 32.f), 4.f));
    int iY = (int)(__fmul_rn(__fadd_rn(y, 32.f), 4.f));
    iX = min(max(iX, 0), 255);
    iY = min(max(iY, 0), 255);
    const int g = iY * 256 + iX;
    const float z  = __ldg(Hmap + g);
    const float nx = __ldg(Nrm + 3 * g + 0);
    const float ny = __ldg(Nrm + 3 * g + 1);
    const float nz = __ldg(Nrm + 3 * g + 2);

    const float lz = __fsub_rn(__fmul_rn(nx, sy), __fmul_rn(ny, cy));
    const float lx = __fsub_rn(0.f, __fmul_rn(nz, sy));
    const float ly = __fmul_rn(nz, cy);
    const float roll = asinf(lz);
    const float fz = __fsub_rn(__fmul_rn(lx, ny), __fmul_rn(ly, nx));
    const float pitch = -asinf(fz);
    rec[2] = z; rec[3] = roll; rec[4] = pitch;

    // ---- roll/pitch boundary exchange + diffs (terminal: x50 == /0.02, ~1ulp) ----
    if (lane == 31) { bnd[w][0] = roll; bnd[w][1] = pitch; }
    __syncthreads();   // (4)
    float pr = __shfl_up_sync(FULLM, roll, 1);
    float pp = __shfl_up_sync(FULLM, pitch, 1);
    if (lane == 0 && w > 0) { pr = bnd[w - 1][0]; pp = bnd[w - 1][1]; }
    float wxv = __fmul_rn(__fsub_rn(roll, pr), 50.0f);
    float wyv = __fmul_rn(__fsub_rn(pitch, pp), 50.0f);
    if (tid == 0) { wxv = rec[12]; wyv = rec[13]; }   // input ch12/13 intact
    const float ay = __fadd_rn(__fmul_rn(vx, wz), __fmul_rn(9.8f, lz));
    const float az = __fadd_rn(__fmul_rn(__fsub_rn(0.f, vx), wyv),
                               __fmul_rn(9.8f, nz));
    rec[10] = ay; rec[11] = az; rec[12] = wxv; rec[13] = wyv;

    __syncthreads();   // (5) image final

    // ---- single bulk DMA: smem -> global ----
    if (tid == 0) {
        float* dst = out_states + (size_t)k * IMG_FLOATS;
        const uint32_t img_s = (uint32_t)__cvta_generic_to_shared(img);
        asm volatile("fence.proxy.async.shared::cta;" ::: "memory");
        asm volatile(
            "cp.async.bulk.global.shared::cta.bulk_group [%0], [%1], %2;"
            :: "l"(dst), "r"(img_s), "r"((uint32_t)IMG_BYTES) : "memory");
        asm volatile("cp.async.bulk.commit_group;" ::: "memory");
        asm volatile("cp.async.bulk.wait_group.read 0;" ::: "memory");
    }
}

extern "C" void kernel_launch(void* const* d_in, const int* in_sizes, int n_in,
                              void* d_out, int out_size)
{
    const float* state = (const float*)d_in[0];
    const float* pact  = (const float*)d_in[1];
    const float* Hmap  = (const float*)d_in[2];
    const float* Nrm   = (const float*)d_in[3];

    const int K = (in_sizes[1] / 2) / T_STEPS;
    float* out_states = (float*)d_out;
    float* out_pa     = (float*)d_out + (size_t)in_sizes[0];

    car_dyn_kernel<<<K, 128>>>(state, pact, Hmap, Nrm, out_states, out_pa);
}

// round 13
// speedup vs baseline: 1.0798x; 1.0078x over previous
#include <cuda_runtime.h>
#include <cstdint>

#define FULLM 0xffffffffu

namespace {
constexpr int T_STEPS = 128;
constexpr int NCH = 17;
constexpr int IMG_FLOATS = T_STEPS * NCH;       // 2176
constexpr int IMG_F4 = IMG_FLOATS / 4;          // 544
constexpr int IMG_BYTES = IMG_FLOATS * 4;       // 8704
}

// ---- JAX Brent-Kung 128-scan, decomposed: per-warp upsweep, 4-wide top
// tree through smem totals, per-warp downsweep with prefix injection.
// Bit-identical to the flat jnp.cumsum association (verified R4-R11). ----

__device__ __forceinline__ float scan_up1(float r, int lane) {
#pragma unroll
    for (int h = 1; h <= 16; h <<= 1) {
        float u = __shfl_up_sync(FULLM, r, h);
        if ((lane & (2 * h - 1)) == (2 * h - 1)) r = __fadd_rn(u, r);
    }
    return r;
}

__device__ __forceinline__ void scan_up2(float& a, float& b, int lane) {
#pragma unroll
    for (int h = 1; h <= 16; h <<= 1) {
        float ua = __shfl_up_sync(FULLM, a, h);
        float ub = __shfl_up_sync(FULLM, b, h);
        if ((lane & (2 * h - 1)) == (2 * h - 1)) {
            a = __fadd_rn(ua, a);
            b = __fadd_rn(ub, b);
        }
    }
}

__device__ __forceinline__ float scan_down1(float r, int lane, int w,
                                            const float* __restrict__ T) {
    const float s1 = __fadd_rn(T[0], T[1]);
    const float S2 = __fadd_rn(s1, T[2]);
    const float S3 = __fadd_rn(s1, __fadd_rn(T[2], T[3]));
    const float E  = (w == 1) ? T[0] : (w == 2) ? s1 : S2;
    const float Sw = (w == 0) ? T[0] : (w == 1) ? s1 : (w == 2) ? S2 : S3;
    if (lane == 31) r = Sw;
#pragma unroll
    for (int h = 16; h >= 1; h >>= 1) {
        float u = __shfl_up_sync(FULLM, r, h);
        if (lane == h - 1) u = E;
        const bool act = ((lane & (2 * h - 1)) == (h - 1)) &&
                         (w > 0 || lane >= 2 * h);
        if (act) r = __fadd_rn(u, r);
    }
    return r;
}

__device__ __forceinline__ void scan_down2(float& a, float& b, int lane, int w,
                                           const float* __restrict__ Ta,
                                           const float* __restrict__ Tb) {
    const float s1a = __fadd_rn(Ta[0], Ta[1]);
    const float S2a = __fadd_rn(s1a, Ta[2]);
    const float S3a = __fadd_rn(s1a, __fadd_rn(Ta[2], Ta[3]));
    const float Ea  = (w == 1) ? Ta[0] : (w == 2) ? s1a : S2a;
    const float Swa = (w == 0) ? Ta[0] : (w == 1) ? s1a : (w == 2) ? S2a : S3a;
    const float s1b = __fadd_rn(Tb[0], Tb[1]);
    const float S2b = __fadd_rn(s1b, Tb[2]);
    const float S3b = __fadd_rn(s1b, __fadd_rn(Tb[2], Tb[3]));
    const float Eb  = (w == 1) ? Tb[0] : (w == 2) ? s1b : S2b;
    const float Swb = (w == 0) ? Tb[0] : (w == 1) ? s1b : (w == 2) ? S2b : S3b;
    if (lane == 31) { a = Swa; b = Swb; }
#pragma unroll
    for (int h = 16; h >= 1; h >>= 1) {
        float ua = __shfl_up_sync(FULLM, a, h);
        float ub = __shfl_up_sync(FULLM, b, h);
        if (lane == h - 1) { ua = Ea; ub = Eb; }
        const bool act = ((lane & (2 * h - 1)) == (h - 1)) &&
                         (w > 0 || lane >= 2 * h);
        if (act) { a = __fadd_rn(ua, a); b = __fadd_rn(ub, b); }
    }
}

__device__ __forceinline__ void cp_async16(float4* dst_smem, const float4* src_gmem) {
    uint32_t s = (uint32_t)__cvta_generic_to_shared(dst_smem);
    asm volatile("cp.async.cg.shared.global [%0], [%1], 16;" ::
                 "r"(s), "l"(src_gmem));
}

__global__ __launch_bounds__(128, 16)
void car_dyn_kernel(const float* __restrict__ state,
                    const float* __restrict__ pact,
                    const float* __restrict__ Hmap,
                    const float* __restrict__ Nrm,
                    float* __restrict__ out_states,
                    float* __restrict__ out_pa)
{
    __shared__ __align__(16) float img[IMG_FLOATS];   // 8704 B working image
    __shared__ float tot[5][4];
    __shared__ float bnd[4][2];

    const int tid  = threadIdx.x;
    const int lane = tid & 31;
    const int w    = tid >> 5;
    const int k    = blockIdx.x;

    float4* img4 = reinterpret_cast<float4*>(img);
    const float4* src4 = reinterpret_cast<const float4*>(state) + (size_t)k * IMG_F4;
#pragma unroll
    for (int i = 0; i < 4; ++i) cp_async16(&img4[tid + 128 * i], &src4[tid + 128 * i]);
    if (tid < 32) cp_async16(&img4[512 + tid], &src4[512 + tid]);
    asm volatile("cp.async.commit_group;" ::: "memory");

    const float2 pa = reinterpret_cast<const float2*>(pact)[(size_t)k * T_STEPS + tid];

    // ---- scans 1&2: cumsum(pa * DT) (overlap with in-copy) ----
    float r0 = __fmul_rn(pa.x, 0.02f);
    float r1 = __fmul_rn(pa.y, 0.02f);
    scan_up2(r0, r1, lane);
    if (lane == 31) { tot[0][w] = r0; tot[1][w] = r1; }

    asm volatile("cp.async.wait_group 0;" ::: "memory");
    __syncthreads();   // (1) image + warp totals ready

    scan_down2(r0, r1, lane, w, tot[0], tot[1]);

    float* rec = img + tid * NCH;   // base 17*tid -> conflict-free scalars

    // ---- controls (clip(clip(v,-1,1),0,0.5) == clip(v,0,0.5), exact) ----
    const float s15 = rec[15], s16 = rec[16];
    float c0 = fminf(fmaxf(__fadd_rn(s15, __fmul_rn(4.0f, r0)), -1.f), 1.f);
    float c1 = fminf(fmaxf(__fadd_rn(s16, __fmul_rn(4.0f, r1)), 0.f), 0.5f);
    const float cm0 = __fsub_rn(c0, s15);
    const float cm1 = __fsub_rn(c1, s16);
    rec[15] = c0; rec[16] = c1;
    rec[7] = 0.f; rec[8] = 0.f;      // vy, vz (ch9 = ax passes through)

    // ---- dynamics elementwise (gather-feeding chain: exact) ----
    const float Kc = __fmul_rn(tanf(c0), 2.0f);       // /0.5 exact
    const float vx = __fmul_rn(c1, 17.0f);
    const float dS = __fmul_rn(vx, 0.02f);
    const float w1 = __fmul_rn(vx, Kc);
    const float a0 = fminf(fmaxf(__fmul_rn(vx, w1), -14.f), 14.f);
    const float wz = __fdiv_rn(a0, fmaxf(vx, 1.f));   // exact: feeds yaw->x,y->gather
    rec[6] = vx; rec[14] = wz;

    // ---- scan 3 upsweep (wz) + cm boundary exchange, one sync ----
    float r2 = scan_up1(wz, lane);
    if (lane == 31) { tot[2][w] = r2; bnd[w][0] = cm0; bnd[w][1] = cm1; }
    __syncthreads();   // (2)

    // ---- new_pa straight to global (terminal output: x12.5 == /0.08, ~1ulp) ----
    {
        float pm0 = __shfl_up_sync(FULLM, cm0, 1);
        float pm1 = __shfl_up_sync(FULLM, cm1, 1);
        if (lane == 0 && w > 0) { pm0 = bnd[w - 1][0]; pm1 = bnd[w - 1][1]; }
        float np0 = __fmul_rn(__fsub_rn(cm0, pm0), 12.5f);
        float np1 = __fmul_rn(__fsub_rn(cm1, pm1), 12.5f);
        if (tid == 0) { np0 = pa.x; np1 = pa.y; }
        reinterpret_cast<float2*>(out_pa)[(size_t)k * T_STEPS + tid] =
            make_float2(np0, np1);
    }

    r2 = scan_down1(r2, lane, w, tot[2]);
    const float yaw = __fadd_rn(rec[5], __fmul_rn(0.02f, r2));
    rec[5] = yaw;
    float sy, cy;
    sincosf(yaw, &sy, &cy);

    // ---- scans 4&5: x, y ----
    float r3 = __fmul_rn(dS, cy);
    float r4 = __fmul_rn(dS, sy);
    scan_up2(r3, r4, lane);
    if (lane == 31) { tot[3][w] = r3; tot[4][w] = r4; }
    __syncthreads();   // (3)
    scan_down2(r3, r4, lane, w, tot[3], tot[4]);
    const float x = __fadd_rn(rec[0], r3);
    const float y = __fadd_rn(rec[1], r4);
    rec[0] = x; rec[1] = y;

    // ---- BEV gather ----
    int iX = (int)(__fmul_rn(__fadd_rn(x, 32.f), 4.f));
    int iY = (int)(__fmul_rn(__fadd_rn(y, 32.f), 4.f));
    iX = min(max(iX, 0), 255);
    iY = min(max(iY, 0), 255);
    const int g = iY * 256 + iX;
    const float z  = __ldg(Hmap + g);
    const float nx = __ldg(Nrm + 3 * g + 0);
    const float ny = __ldg(Nrm + 3 * g + 1);
    const float nz = __ldg(Nrm + 3 * g + 2);

    const float lz = __fsub_rn(__fmul_rn(nx, sy), __fmul_rn(ny, cy));
    const float lx = __fsub_rn(0.f, __fmul_rn(nz, sy));
    const float ly = __fmul_rn(nz, cy);
    const float roll = asinf(lz);
    const float fz = __fsub_rn(__fmul_rn(lx, ny), __fmul_rn(ly, nx));
    const float pitch = -asinf(fz);
    rec[2] = z; rec[3] = roll; rec[4] = pitch;

    // ---- roll/pitch boundary exchange + diffs (terminal: x50 == /0.02, ~1ulp) ----
    if (lane == 31) { bnd[w][0] = roll; bnd[w][1] = pitch; }
    __syncthreads();   // (4)
    float pr = __shfl_up_sync(FULLM, roll, 1);
    float pp = __shfl_up_sync(FULLM, pitch, 1);
    if (lane == 0 && w > 0) { pr = bnd[w - 1][0]; pp = bnd[w - 1][1]; }
    float wxv = __fmul_rn(__fsub_rn(roll, pr), 50.0f);
    float wyv = __fmul_rn(__fsub_rn(pitch, pp), 50.0f);
    if (tid == 0) { wxv = rec[12]; wyv = rec[13]; }   // input ch12/13 intact
    const float ay = __fadd_rn(__fmul_rn(vx, wz), __fmul_rn(9.8f, lz));
    const float az = __fadd_rn(__fmul_rn(__fsub_rn(0.f, vx), wyv),
                               __fmul_rn(9.8f, nz));
    rec[10] = ay; rec[11] = az; rec[12] = wxv; rec[13] = wyv;

    __syncthreads();   // (5) image final

    // ---- single bulk DMA: smem -> global ----
    if (tid == 0) {
        float* dst = out_states + (size_t)k * IMG_FLOATS;
        const uint32_t img_s = (uint32_t)__cvta_generic_to_shared(img);
        asm volatile("fence.proxy.async.shared::cta;" ::: "memory");
        asm volatile(
            "cp.async.bulk.global.shared::cta.bulk_group [%0], [%1], %2;"
            :: "l"(dst), "r"(img_s), "r"((uint32_t)IMG_BYTES) : "memory");
        asm volatile("cp.async.bulk.commit_group;" ::: "memory");
        asm volatile("cp.async.bulk.wait_group.read 0;" ::: "memory");
    }
}

extern "C" void kernel_launch(void* const* d_in, const int* in_sizes, int n_in,
                              void* d_out, int out_size)
{
    const float* state = (const float*)d_in[0];
    const float* pact  = (const float*)d_in[1];
    const float* Hmap  = (const float*)d_in[2];
    const float* Nrm   = (const float*)d_in[3];

    const int K = (in_sizes[1] / 2) / T_STEPS;
    float* out_states = (float*)d_out;
    float* out_pa     = (float*)d_out + (size_t)in_sizes[0];

    car_dyn_kernel<<<K, 128>>>(state, pact, Hmap, Nrm, out_states, out_pa);
}